// round 2
// baseline (speedup 1.0000x reference)
#include <cuda_runtime.h>
#include <stdint.h>

// Fixed problem shape (from reference): N=700000 nodes, H=64 feature width.
#define NMAX 700000
#define HW 64

// Scratch (allocation-free rule: __device__ globals, ~361MB .bss).
__device__ float g_deg[NMAX];
__device__ float g_dinv[NMAX];
__device__ float g_h[(size_t)NMAX * HW];    // h1, then h2
__device__ float g_agg[(size_t)NMAX * HW];  // aggregation accumulator (re-init every call)

// ---------------------------------------------------------------------------
__global__ void k_init_deg(int n) {
    int i = blockIdx.x * blockDim.x + threadIdx.x;
    if (i < n) g_deg[i] = 1.0f;  // self-loop
}

__global__ void k_count_deg(const int* __restrict__ dst, int E) {
    int e = blockIdx.x * blockDim.x + threadIdx.x;
    if (e < E) atomicAdd(&g_deg[dst[e]], 1.0f);
}

__global__ void k_dinv(int n) {
    int i = blockIdx.x * blockDim.x + threadIdx.x;
    if (i < n) g_dinv[i] = rsqrtf(g_deg[i]);
}

// h = x @ W1 ; agg = h * dinv^2 (self-loop init). One warp per row.
__global__ void k_gemm1(const float* __restrict__ x, const float* __restrict__ W1, int n) {
    __shared__ float Ws[32 * 64];
    for (int i = threadIdx.x; i < 32 * 64; i += blockDim.x) Ws[i] = W1[i];
    __syncthreads();
    int warp = threadIdx.x >> 5, lane = threadIdx.x & 31;
    int r = blockIdx.x * 8 + warp;
    if (r >= n) return;
    float xv = x[(size_t)r * 32 + lane];
    float a0 = 0.f, a1 = 0.f;
#pragma unroll
    for (int k = 0; k < 32; k++) {
        float xk = __shfl_sync(0xffffffffu, xv, k);
        a0 = fmaf(xk, Ws[k * 64 + lane], a0);
        a1 = fmaf(xk, Ws[k * 64 + lane + 32], a1);
    }
    size_t base = (size_t)r * 64;
    float di = g_dinv[r], d2 = di * di;
    g_h[base + lane] = a0;
    g_h[base + lane + 32] = a1;
    g_agg[base + lane] = a0 * d2;
    g_agg[base + lane + 32] = a1 * d2;
}

// Edge scatter: agg[dst] += h[src] * dinv[src]*dinv[dst]. One warp per edge,
// each lane owns 2 contiguous floats (float2 gather, 2 RED.ADD.F32).
__global__ void k_edge(const int* __restrict__ src,
                       const int* __restrict__ dst, int E) {
    int e = blockIdx.x * 8 + (threadIdx.x >> 5);
    if (e >= E) return;
    int lane = threadIdx.x & 31;
    int s = src[e], d = dst[e];                // uniform per warp -> broadcast
    float coef = g_dinv[s] * g_dinv[d];
    const float2 v = *(const float2*)(g_h + (size_t)s * 64 + lane * 2);
    float* ap = g_agg + (size_t)d * 64 + lane * 2;
    atomicAdd(ap, v.x * coef);
    atomicAdd(ap + 1, v.y * coef);
}

// h2 = relu(agg + b1) @ W2 ; agg re-init (in-place, row-local) = h2 * dinv^2.
__global__ void k_gemm2(const float* __restrict__ W2, const float* __restrict__ b1, int n) {
    __shared__ float Ws[64 * 64];
    __shared__ float rowbuf[8][64];
    for (int i = threadIdx.x; i < 64 * 64; i += blockDim.x) Ws[i] = W2[i];
    __syncthreads();
    int warp = threadIdx.x >> 5, lane = threadIdx.x & 31;
    int r = blockIdx.x * 8 + warp;
    if (r >= n) return;
    size_t base = (size_t)r * 64;
    float2 av = *(const float2*)(g_agg + base + (size_t)lane * 2);
    rowbuf[warp][lane * 2]     = fmaxf(av.x + b1[lane * 2], 0.f);
    rowbuf[warp][lane * 2 + 1] = fmaxf(av.y + b1[lane * 2 + 1], 0.f);
    __syncwarp();
    float a0 = 0.f, a1 = 0.f;
#pragma unroll
    for (int k = 0; k < 64; k++) {
        float ak = rowbuf[warp][k];
        a0 = fmaf(ak, Ws[k * 64 + lane], a0);
        a1 = fmaf(ak, Ws[k * 64 + lane + 32], a1);
    }
    float di = g_dinv[r], d2 = di * di;
    g_h[base + lane] = a0;
    g_h[base + lane + 32] = a1;
    g_agg[base + lane] = a0 * d2;
    g_agg[base + lane + 32] = a1 * d2;
}

// out[g] = relu(agg[g,:] + b2_bcast) . Wfc + bfc.  One warp per graph (896 elems).
__global__ void k_final(const float* __restrict__ b2, const float* __restrict__ Wfc,
                        const float* __restrict__ bfc, float* __restrict__ out, int B) {
    __shared__ float Ws[896];
    __shared__ float bs[64];
    for (int i = threadIdx.x; i < 896; i += blockDim.x) Ws[i] = Wfc[i];
    if (threadIdx.x < 64) bs[threadIdx.x] = b2[threadIdx.x];
    __syncthreads();
    int warp = threadIdx.x >> 5, lane = threadIdx.x & 31;
    int g = blockIdx.x * 8 + warp;
    if (g >= B) return;
    const float* row = g_agg + (size_t)g * 896;
    float acc = 0.f;
#pragma unroll
    for (int j = 0; j < 7; j++) {
        int idx = (j * 32 + lane) * 4;
        float4 v = *(const float4*)(row + idx);
        acc = fmaf(fmaxf(v.x + bs[idx & 63], 0.f), Ws[idx], acc);
        acc = fmaf(fmaxf(v.y + bs[(idx + 1) & 63], 0.f), Ws[idx + 1], acc);
        acc = fmaf(fmaxf(v.z + bs[(idx + 2) & 63], 0.f), Ws[idx + 2], acc);
        acc = fmaf(fmaxf(v.w + bs[(idx + 3) & 63], 0.f), Ws[idx + 3], acc);
    }
#pragma unroll
    for (int o = 16; o; o >>= 1) acc += __shfl_down_sync(0xffffffffu, acc, o);
    if (lane == 0) out[g] = acc + bfc[0];
}

// ---------------------------------------------------------------------------
extern "C" void kernel_launch(void* const* d_in, const int* in_sizes, int n_in,
                              void* d_out, int out_size) {
    const float* x    = (const float*)d_in[0];
    const int*   edges = (const int*)d_in[1];   // int32: JAX x64 disabled downcasts int64
    const float* W1   = (const float*)d_in[2];
    const float* b1   = (const float*)d_in[3];
    const float* W2   = (const float*)d_in[4];
    const float* b2   = (const float*)d_in[5];
    const float* Wfc  = (const float*)d_in[6];
    const float* bfc  = (const float*)d_in[7];
    float* out = (float*)d_out;

    int n = in_sizes[0] / 32;   // 700000
    int E = in_sizes[1] / 2;    // 4000000
    int B = n / 14;             // 50000
    const int* src = edges;
    const int* dst = edges + E;

    k_init_deg<<<(n + 255) / 256, 256>>>(n);
    k_count_deg<<<(E + 255) / 256, 256>>>(dst, E);
    k_dinv<<<(n + 255) / 256, 256>>>(n);

    // Layer 1
    k_gemm1<<<(n + 7) / 8, 256>>>(x, W1, n);
    k_edge<<<(E + 7) / 8, 256>>>(src, dst, E);

    // Layer 2 (fused relu+bias+GEMM+self-loop re-init)
    k_gemm2<<<(n + 7) / 8, 256>>>(W2, b1, n);
    k_edge<<<(E + 7) / 8, 256>>>(src, dst, E);

    // FC head
    k_final<<<(B + 7) / 8, 256>>>(b2, Wfc, bfc, out, B);
}